// round 3
// baseline (speedup 1.0000x reference)
#include <cuda_runtime.h>
#include <math.h>

#define TT 256
#define BB 64
#define HH 512
#define NG 4
#define RC_CTAS 128

typedef unsigned long long ull;

// -------- scratch (__device__ globals; no allocation allowed) --------
static __device__ float g_gx[(size_t)2 * NG * TT * BB * HH];   // [d][g][t][b][h]
static __device__ float g_out0[(size_t)TT * BB * 2 * HH];      // layer0 output [t][b][2H]
static __device__ float g_gates[(size_t)2 * NG * BB * HH];     // [d][g][b][h]
static __device__ float g_h[2 * BB * HH];
static __device__ float g_c[2 * BB * HH];
static __device__ unsigned g_bar_count;
static __device__ volatile unsigned g_bar_gen;

// -------------------- f32x2 packed helpers --------------------
__device__ __forceinline__ void ffma2(ull& d, ull a, ull b) {
    asm("fma.rn.f32x2 %0, %1, %2, %0;" : "+l"(d) : "l"(a), "l"(b));
}
__device__ __forceinline__ float2 unpack2(ull v) {
    float2 r;
    asm("mov.b64 {%0, %1}, %2;" : "=f"(r.x), "=f"(r.y) : "l"(v));
    return r;
}

// -------------------- software grid barrier --------------------
__device__ __forceinline__ void grid_barrier() {
    __syncthreads();
    if (threadIdx.x == 0) {
        unsigned gen = g_bar_gen;
        __threadfence();
        if (atomicAdd(&g_bar_count, 1) == RC_CTAS - 1) {
            atomicExch(&g_bar_count, 0);
            __threadfence();
            atomicAdd((unsigned*)&g_bar_gen, 1);
        } else {
            while (g_bar_gen == gen) {}
            __threadfence();
        }
    }
    __syncthreads();
}

// -------------------- gx GEMM --------------------
// For (d,g): C[t*B+b][h] = sum_k X[t*B+b][k]*Noise[dg][b][k]*W[dg][k][h] + (b_ih+b_hh)
// BM=64 (batch rows of one t), BN=64, BK=16, 128 threads, per-thread 8x4 via f32x2.
template<int K>
__global__ __launch_bounds__(128)
void gx_gemm_kernel(const float* __restrict__ X,
                    const float* __restrict__ Noise,
                    const float* __restrict__ W,
                    const float* __restrict__ bih,
                    const float* __restrict__ bhh)
{
    const int dg = blockIdx.z;   // 0..7
    const int mt = blockIdx.y;   // t
    const int nt = blockIdx.x;   // 0..7 (64 cols each)
    const int tid = threadIdx.x;

    __shared__ float As[16][68];    // [k][b]
    __shared__ float Bs[16][136];   // [k][2n] duplicated pairs

    const float* Xbase = (K == 1024) ? (const float*)g_out0 : X;
    const float* Xp = Xbase + (size_t)mt * BB * K;
    const float* Np = Noise + (size_t)dg * BB * K;
    const float* Wp = W + (size_t)dg * K * HH + nt * 64;

    ull accp[4][4];   // [batch-pair][col]
    #pragma unroll
    for (int p = 0; p < 4; p++)
        #pragma unroll
        for (int j = 0; j < 4; j++) accp[p][j] = 0ULL;

    const int a_lm = tid >> 2;          // 0..31
    const int a_lk = (tid & 3) * 4;     // 0,4,8,12
    const int b_lk = tid >> 4;          // 0..7
    const int b_ln = (tid & 15) * 4;    // 0..60
    const int tm = (tid >> 4) * 8;      // 0..56 (8 batch rows)
    const int tn = (tid & 15) * 4;      // 0..60 (4 cols)

    for (int k0 = 0; k0 < K; k0 += 16) {
        #pragma unroll
        for (int p = 0; p < 2; p++) {
            int lm = a_lm + p * 32;
            float4 xv = *reinterpret_cast<const float4*>(Xp + (size_t)lm * K + k0 + a_lk);
            float4 nv = *reinterpret_cast<const float4*>(Np + (size_t)lm * K + k0 + a_lk);
            As[a_lk + 0][lm] = xv.x * nv.x;
            As[a_lk + 1][lm] = xv.y * nv.y;
            As[a_lk + 2][lm] = xv.z * nv.z;
            As[a_lk + 3][lm] = xv.w * nv.w;
        }
        #pragma unroll
        for (int p = 0; p < 2; p++) {
            int lk = b_lk + p * 8;
            float4 w = *reinterpret_cast<const float4*>(Wp + (size_t)(k0 + lk) * HH + b_ln);
            float4 d0 = make_float4(w.x, w.x, w.y, w.y);
            float4 d1 = make_float4(w.z, w.z, w.w, w.w);
            *reinterpret_cast<float4*>(&Bs[lk][b_ln * 2])     = d0;
            *reinterpret_cast<float4*>(&Bs[lk][b_ln * 2 + 4]) = d1;
        }
        __syncthreads();

        #pragma unroll
        for (int kk = 0; kk < 16; kk++) {
            ulonglong2 av0 = *reinterpret_cast<const ulonglong2*>(&As[kk][tm]);
            ulonglong2 av1 = *reinterpret_cast<const ulonglong2*>(&As[kk][tm + 4]);
            ulonglong2 bv0 = *reinterpret_cast<const ulonglong2*>(&Bs[kk][tn * 2]);
            ulonglong2 bv1 = *reinterpret_cast<const ulonglong2*>(&Bs[kk][tn * 2 + 4]);
            ull a[4] = {av0.x, av0.y, av1.x, av1.y};
            ull b[4] = {bv0.x, bv0.y, bv1.x, bv1.y};
            #pragma unroll
            for (int p = 0; p < 4; p++)
                #pragma unroll
                for (int j = 0; j < 4; j++)
                    ffma2(accp[p][j], a[p], b[j]);
        }
        __syncthreads();
    }

    float bias[4];
    #pragma unroll
    for (int j = 0; j < 4; j++)
        bias[j] = bih[dg * HH + nt * 64 + tn + j] + bhh[dg * HH + nt * 64 + tn + j];

    float* Cp = g_gx + ((size_t)dg * TT + mt) * BB * HH;
    #pragma unroll
    for (int p = 0; p < 4; p++) {
        float2 u[4];
        #pragma unroll
        for (int j = 0; j < 4; j++) u[j] = unpack2(accp[p][j]);
        // batch tm+2p (lo lane)
        float4 v0 = make_float4(u[0].x + bias[0], u[1].x + bias[1],
                                u[2].x + bias[2], u[3].x + bias[3]);
        // batch tm+2p+1 (hi lane)
        float4 v1 = make_float4(u[0].y + bias[0], u[1].y + bias[1],
                                u[2].y + bias[2], u[3].y + bias[3]);
        *reinterpret_cast<float4*>(Cp + (size_t)(tm + 2 * p) * HH + nt * 64 + tn) = v0;
        *reinterpret_cast<float4*>(Cp + (size_t)(tm + 2 * p + 1) * HH + nt * 64 + tn) = v1;
    }
}

// -------------------- persistent recurrence kernel --------------------
// grid = 128 CTAs (co-resident), 256 threads.
// CTA cta: dg = cta>>4 (dir*4+gate), nt = cta&15 -> cols [nt*32, nt*32+32) of that gate.
// w_hh slice held duplicated in dynamic SMEM across all 256 steps.
__global__ __launch_bounds__(256, 1)
void recur_kernel(const float* __restrict__ Whh,
                  const float* __restrict__ NoiseH,
                  const float* __restrict__ mask,
                  float* __restrict__ outp,          // layer1: d_out; layer0: ignored
                  int layer,
                  float* __restrict__ hn,
                  float* __restrict__ cn)
{
    extern __shared__ float Ws[];        // [512][64] duplicated pairs = 128KB
    __shared__ float As[16][68];         // [k][b]

    const int cta = blockIdx.x;
    const int dg  = cta >> 4;
    const int d   = dg >> 2;
    const int nt  = cta & 15;
    const int tid = threadIdx.x;

    float* op = (layer == 0) ? (float*)g_out0 : outp;

    const float* Hp = g_h + (size_t)d * BB * HH;
    const float* Np = NoiseH + (size_t)dg * BB * HH;
    const float* Wp = Whh + (size_t)dg * HH * HH + nt * 32;

    // Load W slice duplicated: Ws[k][2c], Ws[k][2c+1] = W[k][c]
    for (int i = tid; i < 512 * 8; i += 256) {
        int k = i >> 3;
        int c4 = (i & 7) * 4;
        float4 w = *reinterpret_cast<const float4*>(Wp + (size_t)k * HH + c4);
        *reinterpret_cast<float4*>(&Ws[k * 64 + c4 * 2])     = make_float4(w.x, w.x, w.y, w.y);
        *reinterpret_cast<float4*>(&Ws[k * 64 + c4 * 2 + 4]) = make_float4(w.z, w.z, w.w, w.w);
    }
    // Zero h/c state (each CTA zeroes its 512-element slice of the 65536)
    for (int i = tid; i < 512; i += 256) {
        g_h[cta * 512 + i] = 0.f;
        g_c[cta * 512 + i] = 0.f;
    }
    grid_barrier();

    const int tc = (tid & 15) * 2;   // col pair within 32
    const int tm = (tid >> 4) * 4;   // 4 batch rows

    for (int step = 0; step < TT; ++step) {
        const int t = (d == 0) ? step : (TT - 1 - step);

        // ---- GEMM phase: gates[dg][b][nt*32+c] = gx + (h*noise) @ Whh-slice ----
        ull acc00 = 0, acc01 = 0, acc10 = 0, acc11 = 0;

        for (int k0 = 0; k0 < HH; k0 += 16) {
            __syncthreads();
            {
                int b  = tid & 63;
                int kq = tid >> 6;             // 0..3
                float4 hv = *reinterpret_cast<const float4*>(Hp + (size_t)b * HH + k0 + kq * 4);
                float4 nv = *reinterpret_cast<const float4*>(Np + (size_t)b * HH + k0 + kq * 4);
                As[kq * 4 + 0][b] = hv.x * nv.x;
                As[kq * 4 + 1][b] = hv.y * nv.y;
                As[kq * 4 + 2][b] = hv.z * nv.z;
                As[kq * 4 + 3][b] = hv.w * nv.w;
            }
            __syncthreads();

            #pragma unroll
            for (int kk = 0; kk < 16; kk++) {
                ulonglong2 av = *reinterpret_cast<const ulonglong2*>(&As[kk][tm]);
                ulonglong2 wv = *reinterpret_cast<const ulonglong2*>(&Ws[(k0 + kk) * 64 + tc * 2]);
                ffma2(acc00, av.x, wv.x);
                ffma2(acc01, av.x, wv.y);
                ffma2(acc10, av.y, wv.x);
                ffma2(acc11, av.y, wv.y);
            }
        }

        {
            const float* gxp = g_gx + ((size_t)dg * TT + t) * BB * HH;
            float* gp = g_gates + (size_t)dg * BB * HH;
            const int col = nt * 32 + tc;
            float2 r00 = unpack2(acc00);  // batches tm, tm+1 @ col
            float2 r01 = unpack2(acc01);  // batches tm, tm+1 @ col+1
            float2 r10 = unpack2(acc10);  // batches tm+2, tm+3 @ col
            float2 r11 = unpack2(acc11);

            float2 gx0 = *reinterpret_cast<const float2*>(gxp + (size_t)(tm + 0) * HH + col);
            float2 gx1 = *reinterpret_cast<const float2*>(gxp + (size_t)(tm + 1) * HH + col);
            float2 gx2 = *reinterpret_cast<const float2*>(gxp + (size_t)(tm + 2) * HH + col);
            float2 gx3 = *reinterpret_cast<const float2*>(gxp + (size_t)(tm + 3) * HH + col);

            *reinterpret_cast<float2*>(gp + (size_t)(tm + 0) * HH + col) =
                make_float2(r00.x + gx0.x, r01.x + gx0.y);
            *reinterpret_cast<float2*>(gp + (size_t)(tm + 1) * HH + col) =
                make_float2(r00.y + gx1.x, r01.y + gx1.y);
            *reinterpret_cast<float2*>(gp + (size_t)(tm + 2) * HH + col) =
                make_float2(r10.x + gx2.x, r11.x + gx2.y);
            *reinterpret_cast<float2*>(gp + (size_t)(tm + 3) * HH + col) =
                make_float2(r10.y + gx3.x, r11.y + gx3.y);
        }

        grid_barrier();

        // ---- pointwise LSTM cell: 65536 elems, 512 per CTA, 2 per thread ----
        {
            int base = cta * 512 + tid * 2;
            int d2  = base >> 15;
            int rem = base & 32767;
            int b   = rem >> 9;
            int h   = rem & 511;
            int t2  = (d2 == 0) ? step : (TT - 1 - step);

            const float* gb = g_gates + (size_t)d2 * NG * BB * HH + (size_t)b * HH + h;
            float2 gi = *reinterpret_cast<const float2*>(gb);
            float2 gf = *reinterpret_cast<const float2*>(gb + (size_t)BB * HH);
            float2 gg = *reinterpret_cast<const float2*>(gb + (size_t)2 * BB * HH);
            float2 go = *reinterpret_cast<const float2*>(gb + (size_t)3 * BB * HH);

            size_t sidx = (size_t)d2 * BB * HH + (size_t)b * HH + h;
            float2 cp = *reinterpret_cast<float2*>(&g_c[sidx]);
            float2 hp = *reinterpret_cast<float2*>(&g_h[sidx]);
            float mt = mask[t2 * BB + b];

            float2 hm, cm;
            {
                float ii = 1.f / (1.f + expf(-gi.x));
                float ff = 1.f / (1.f + expf(-gf.x));
                float g2 = tanhf(gg.x);
                float oo = 1.f / (1.f + expf(-go.x));
                float cnew = ff * cp.x + ii * g2;
                float hnew = oo * tanhf(cnew);
                hm.x = hnew * mt + hp.x * (1.f - mt);
                cm.x = cnew * mt + cp.x * (1.f - mt);
            }
            {
                float ii = 1.f / (1.f + expf(-gi.y));
                float ff = 1.f / (1.f + expf(-gf.y));
                float g2 = tanhf(gg.y);
                float oo = 1.f / (1.f + expf(-go.y));
                float cnew = ff * cp.y + ii * g2;
                float hnew = oo * tanhf(cnew);
                hm.y = hnew * mt + hp.y * (1.f - mt);
                cm.y = cnew * mt + cp.y * (1.f - mt);
            }

            *reinterpret_cast<float2*>(&g_h[sidx]) = hm;
            *reinterpret_cast<float2*>(&g_c[sidx]) = cm;

            *reinterpret_cast<float2*>(op + (size_t)t2 * BB * 2 * HH +
                                       (size_t)b * 2 * HH + d2 * HH + h) = hm;

            if (step == TT - 1) {
                size_t oi = ((size_t)(layer * 2 + d2) * BB + b) * HH + h;
                *reinterpret_cast<float2*>(hn + oi) = hm;
                *reinterpret_cast<float2*>(cn + oi) = cm;
            }
        }

        grid_barrier();
    }
}

// -------------------- launch --------------------
extern "C" void kernel_launch(void* const* d_in, const int* in_sizes, int n_in,
                              void* d_out, int out_size)
{
    const float* x      = (const float*)d_in[0];
    const float* mask   = (const float*)d_in[1];
    const float* w_ih0  = (const float*)d_in[2];
    const float* w_hh0  = (const float*)d_in[3];
    const float* b_ih0  = (const float*)d_in[4];
    const float* b_hh0  = (const float*)d_in[5];
    const float* n_in0  = (const float*)d_in[6];
    const float* n_hid0 = (const float*)d_in[7];
    const float* w_ih1  = (const float*)d_in[8];
    const float* w_hh1  = (const float*)d_in[9];
    const float* b_ih1  = (const float*)d_in[10];
    const float* b_hh1  = (const float*)d_in[11];
    const float* n_in1  = (const float*)d_in[12];
    const float* n_hid1 = (const float*)d_in[13];

    float* out  = (float*)d_out;
    float* out1 = out;                                  // [T][B][2H]
    float* hn   = out + (size_t)TT * BB * 2 * HH;       // [4][B][H]
    float* cn   = hn + (size_t)4 * BB * HH;             // [4][B][H]

    static bool attr_set = false;
    if (!attr_set) {
        cudaFuncSetAttribute(recur_kernel,
                             cudaFuncAttributeMaxDynamicSharedMemorySize, 131072);
        attr_set = true;
    }

    dim3 gxgrid(HH / 64, TT, 8);

    // layer 0
    gx_gemm_kernel<512><<<gxgrid, 128>>>(x, n_in0, w_ih0, b_ih0, b_hh0);
    recur_kernel<<<RC_CTAS, 256, 131072>>>(w_hh0, n_hid0, mask, out1, 0, hn, cn);

    // layer 1
    gx_gemm_kernel<1024><<<gxgrid, 128>>>(nullptr, n_in1, w_ih1, b_ih1, b_hh1);
    recur_kernel<<<RC_CTAS, 256, 131072>>>(w_hh1, n_hid1, mask, out1, 1, hn, cn);
}

// round 4
// speedup vs baseline: 1.3957x; 1.3957x over previous
#include <cuda_runtime.h>
#include <stdint.h>

#define TT 256
#define BB 64
#define HH 512
#define RC_CTAS 128

typedef unsigned long long ull;

// -------- scratch (__device__ globals) --------
static __device__ float g_gx[(size_t)8 * TT * BB * HH];      // [dg][t][b][h]
static __device__ float g_out0[(size_t)TT * BB * 2 * HH];    // [t][b][2H]
static __device__ float g_gates[8 * HH * BB];                // [dg][h][b]
static __device__ float g_A[8 * HH * BB];                    // [dg][k][b]  (= h*noise)
static __device__ float g_noiseT[8 * HH * BB];               // [dg][h][b]
static __device__ float g_h[2 * HH * BB];                    // [d][h][b]
static __device__ float g_c[2 * HH * BB];                    // [d][h][b]
static __device__ unsigned g_bar_count;
static __device__ unsigned g_bar_gen;

// -------------------- helpers --------------------
__device__ __forceinline__ void ffma2(ull& d, ull a, ull b) {
    asm("fma.rn.f32x2 %0, %1, %2, %0;" : "+l"(d) : "l"(a), "l"(b));
}
__device__ __forceinline__ float2 unpack2(ull v) {
    float2 r;
    asm("mov.b64 {%0, %1}, %2;" : "=f"(r.x), "=f"(r.y) : "l"(v));
    return r;
}
__device__ __forceinline__ void cp_async16(uint32_t s, const void* g) {
    asm volatile("cp.async.ca.shared.global [%0], [%1], 16;" :: "r"(s), "l"(g));
}
__device__ __forceinline__ float fsig(float x) {
    return __fdividef(1.f, 1.f + __expf(-x));
}
__device__ __forceinline__ float ftanh(float x) {
    return 2.f * fsig(2.f * x) - 1.f;   // exact identity; fast sigmoid
}

// -------------------- grid barrier (acq/rel, gpu scope) --------------------
__device__ __forceinline__ void grid_barrier() {
    __syncthreads();
    if (threadIdx.x == 0) {
        unsigned gen;
        asm volatile("ld.acquire.gpu.global.u32 %0, [%1];"
                     : "=r"(gen) : "l"(&g_bar_gen) : "memory");
        unsigned old;
        asm volatile("atom.acq_rel.gpu.global.add.u32 %0, [%1], 1;"
                     : "=r"(old) : "l"(&g_bar_count) : "memory");
        if (old == RC_CTAS - 1) {
            asm volatile("st.relaxed.gpu.global.u32 [%0], %1;"
                         :: "l"(&g_bar_count), "r"(0u) : "memory");
            asm volatile("st.release.gpu.global.u32 [%0], %1;"
                         :: "l"(&g_bar_gen), "r"(gen + 1) : "memory");
        } else {
            unsigned cur;
            do {
                asm volatile("ld.acquire.gpu.global.u32 %0, [%1];"
                             : "=r"(cur) : "l"(&g_bar_gen) : "memory");
            } while (cur == gen);
        }
    }
    __syncthreads();
}

// -------------------- noise transpose: [dg][b][h] -> [dg][h][b] --------------------
__global__ void noiseT_kernel(const float* __restrict__ nh) {
    __shared__ float tile[32][33];
    int dg = blockIdx.z;
    int h0 = blockIdx.x * 32, b0 = blockIdx.y * 32;
    int x = threadIdx.x, y = threadIdx.y;   // 32 x 8
    #pragma unroll
    for (int i = 0; i < 32; i += 8)
        tile[y + i][x] = nh[(size_t)dg * BB * HH + (size_t)(b0 + y + i) * HH + h0 + x];
    __syncthreads();
    #pragma unroll
    for (int i = 0; i < 32; i += 8)
        g_noiseT[(size_t)dg * HH * BB + (size_t)(h0 + y + i) * BB + b0 + x] = tile[x][y + i];
}

// -------------------- gx GEMM (unchanged from R3) --------------------
template<int K>
__global__ __launch_bounds__(128)
void gx_gemm_kernel(const float* __restrict__ X,
                    const float* __restrict__ Noise,
                    const float* __restrict__ W,
                    const float* __restrict__ bih,
                    const float* __restrict__ bhh)
{
    const int dg = blockIdx.z;
    const int mt = blockIdx.y;
    const int nt = blockIdx.x;
    const int tid = threadIdx.x;

    __shared__ float As[16][68];
    __shared__ float Bs[16][136];

    const float* Xbase = (K == 1024) ? (const float*)g_out0 : X;
    const float* Xp = Xbase + (size_t)mt * BB * K;
    const float* Np = Noise + (size_t)dg * BB * K;
    const float* Wp = W + (size_t)dg * K * HH + nt * 64;

    ull accp[4][4];
    #pragma unroll
    for (int p = 0; p < 4; p++)
        #pragma unroll
        for (int j = 0; j < 4; j++) accp[p][j] = 0ULL;

    const int a_lm = tid >> 2;
    const int a_lk = (tid & 3) * 4;
    const int b_lk = tid >> 4;
    const int b_ln = (tid & 15) * 4;
    const int tm = (tid >> 4) * 8;
    const int tn = (tid & 15) * 4;

    for (int k0 = 0; k0 < K; k0 += 16) {
        #pragma unroll
        for (int p = 0; p < 2; p++) {
            int lm = a_lm + p * 32;
            float4 xv = *reinterpret_cast<const float4*>(Xp + (size_t)lm * K + k0 + a_lk);
            float4 nv = *reinterpret_cast<const float4*>(Np + (size_t)lm * K + k0 + a_lk);
            As[a_lk + 0][lm] = xv.x * nv.x;
            As[a_lk + 1][lm] = xv.y * nv.y;
            As[a_lk + 2][lm] = xv.z * nv.z;
            As[a_lk + 3][lm] = xv.w * nv.w;
        }
        #pragma unroll
        for (int p = 0; p < 2; p++) {
            int lk = b_lk + p * 8;
            float4 w = *reinterpret_cast<const float4*>(Wp + (size_t)(k0 + lk) * HH + b_ln);
            *reinterpret_cast<float4*>(&Bs[lk][b_ln * 2])     = make_float4(w.x, w.x, w.y, w.y);
            *reinterpret_cast<float4*>(&Bs[lk][b_ln * 2 + 4]) = make_float4(w.z, w.z, w.w, w.w);
        }
        __syncthreads();

        #pragma unroll
        for (int kk = 0; kk < 16; kk++) {
            ulonglong2 av0 = *reinterpret_cast<const ulonglong2*>(&As[kk][tm]);
            ulonglong2 av1 = *reinterpret_cast<const ulonglong2*>(&As[kk][tm + 4]);
            ulonglong2 bv0 = *reinterpret_cast<const ulonglong2*>(&Bs[kk][tn * 2]);
            ulonglong2 bv1 = *reinterpret_cast<const ulonglong2*>(&Bs[kk][tn * 2 + 4]);
            ull a[4] = {av0.x, av0.y, av1.x, av1.y};
            ull b[4] = {bv0.x, bv0.y, bv1.x, bv1.y};
            #pragma unroll
            for (int p = 0; p < 4; p++)
                #pragma unroll
                for (int j = 0; j < 4; j++)
                    ffma2(accp[p][j], a[p], b[j]);
        }
        __syncthreads();
    }

    float bias[4];
    #pragma unroll
    for (int j = 0; j < 4; j++)
        bias[j] = bih[dg * HH + nt * 64 + tn + j] + bhh[dg * HH + nt * 64 + tn + j];

    float* Cp = g_gx + ((size_t)dg * TT + mt) * BB * HH;
    #pragma unroll
    for (int p = 0; p < 4; p++) {
        float2 u[4];
        #pragma unroll
        for (int j = 0; j < 4; j++) u[j] = unpack2(accp[p][j]);
        float4 v0 = make_float4(u[0].x + bias[0], u[1].x + bias[1],
                                u[2].x + bias[2], u[3].x + bias[3]);
        float4 v1 = make_float4(u[0].y + bias[0], u[1].y + bias[1],
                                u[2].y + bias[2], u[3].y + bias[3]);
        *reinterpret_cast<float4*>(Cp + (size_t)(tm + 2 * p) * HH + nt * 64 + tn) = v0;
        *reinterpret_cast<float4*>(Cp + (size_t)(tm + 2 * p + 1) * HH + nt * 64 + tn) = v1;
    }
}

// -------------------- persistent recurrence --------------------
// CTA cta: dg = cta>>4, nt = cta&15 -> 32 cols of gate dg.
// Ws: w_hh slice duplicated [512][64] in dynamic smem (128KB).
// As: double-buffered cp.async staging of precomputed A chunks [2][16][64].
__global__ __launch_bounds__(256, 1)
void recur_kernel(const float* __restrict__ Whh,
                  const float* __restrict__ mask,
                  float* __restrict__ outp,
                  int layer,
                  float* __restrict__ hn,
                  float* __restrict__ cn)
{
    extern __shared__ float Ws[];                 // [512][64] duplicated = 128KB
    __shared__ __align__(16) float Asb[2][16][64];  // 8KB

    const int cta = blockIdx.x;
    const int dg  = cta >> 4;
    const int d   = dg >> 2;
    const int nt  = cta & 15;
    const int tid = threadIdx.x;

    float* op = (layer == 0) ? (float*)g_out0 : outp;

    // ---- load W slice duplicated: Ws[k][4*tc+{0,1}] = W[k][2tc], [4*tc+{2,3}] = W[k][2tc+1]
    {
        const float* Wp = Whh + (size_t)dg * HH * HH + nt * 32;
        for (int i = tid; i < 512 * 8; i += 256) {
            int k = i >> 3;
            int c4 = (i & 7) * 4;
            float4 w = *reinterpret_cast<const float4*>(Wp + (size_t)k * HH + c4);
            *reinterpret_cast<float4*>(&Ws[k * 64 + c4 * 2])     = make_float4(w.x, w.x, w.y, w.y);
            *reinterpret_cast<float4*>(&Ws[k * 64 + c4 * 2 + 4]) = make_float4(w.z, w.z, w.w, w.w);
        }
    }
    // ---- zero state slices
    for (int i = tid; i < 512; i += 256) { g_h[cta * 512 + i] = 0.f; g_c[cta * 512 + i] = 0.f; }
    for (int i = tid; i < 2048; i += 256) g_A[cta * 2048 + i] = 0.f;
    grid_barrier();

    // warp tile mapping: 8 col-pairs x 4 batch-groups per warp
    const int tc = ((tid >> 5) & 1) * 8 + (tid & 7);          // 0..15 col-pair
    const int tm = (((tid >> 6) << 2) + ((tid >> 3) & 3)) * 4; // 0..60 batch base
    const float* Abase = g_A + (size_t)dg * HH * BB;
    const uint32_t as_u32 = (uint32_t)__cvta_generic_to_shared(&Asb[0][0][0]);
    const float* wsp = Ws + tc * 4;

    for (int step = 0; step < TT; ++step) {
        const int t = (d == 0) ? step : (TT - 1 - step);

        // prefetch gx for epilogue (hides DRAM latency behind GEMM)
        const float* gxp = g_gx + ((size_t)dg * TT + t) * BB * HH;
        const int c0 = nt * 32 + tc * 2;
        float2 gxb[4];
        #pragma unroll
        for (int p = 0; p < 4; p++)
            gxb[p] = *reinterpret_cast<const float2*>(gxp + (size_t)(tm + p) * HH + c0);

        // ---- GEMM: gates[b][c] = gx + A @ W-slice, cp.async double-buffered ----
        cp_async16(as_u32 + tid * 16, Abase + tid * 4);
        asm volatile("cp.async.commit_group;");

        ull a00 = 0, a01 = 0, a10 = 0, a11 = 0;
        #pragma unroll 1
        for (int ch = 0; ch < 32; ++ch) {
            asm volatile("cp.async.wait_group 0;");
            __syncthreads();
            if (ch < 31)
                cp_async16(as_u32 + (((ch + 1) & 1) << 12) + tid * 16,
                           Abase + (ch + 1) * 1024 + tid * 4);
            asm volatile("cp.async.commit_group;");

            const float* asr = &Asb[ch & 1][0][0];
            const float* wr  = wsp + ch * 16 * 64;
            #pragma unroll
            for (int kk = 0; kk < 16; kk++) {
                ulonglong2 a2 = *reinterpret_cast<const ulonglong2*>(asr + kk * 64 + tm);
                ulonglong2 w2 = *reinterpret_cast<const ulonglong2*>(wr + kk * 64);
                ffma2(a00, a2.x, w2.x);
                ffma2(a01, a2.y, w2.x);
                ffma2(a10, a2.x, w2.y);
                ffma2(a11, a2.y, w2.y);
            }
        }

        // ---- epilogue: gates[dg][c][b] = acc + gx ----
        {
            float2 u00 = unpack2(a00), u01 = unpack2(a01);
            float2 u10 = unpack2(a10), u11 = unpack2(a11);
            float4 v0 = make_float4(u00.x + gxb[0].x, u00.y + gxb[1].x,
                                    u01.x + gxb[2].x, u01.y + gxb[3].x);
            float4 v1 = make_float4(u10.x + gxb[0].y, u10.y + gxb[1].y,
                                    u11.x + gxb[2].y, u11.y + gxb[3].y);
            *reinterpret_cast<float4*>(g_gates + ((size_t)dg * HH + c0) * BB + tm) = v0;
            *reinterpret_cast<float4*>(g_gates + ((size_t)dg * HH + c0 + 1) * BB + tm) = v1;
        }

        grid_barrier();

        // ---- pointwise: thread <-> (d2, h, b-pair), all accesses coalesced ----
        {
            int idx = cta * 512 + tid * 2;
            int d2  = idx >> 15;
            int rem = idx & 32767;
            int h   = rem >> 6;
            int b   = rem & 63;
            int t2  = (d2 == 0) ? step : (TT - 1 - step);

            const float* gb = g_gates + ((size_t)d2 * 4 * HH + h) * BB + b;
            float2 gi = *reinterpret_cast<const float2*>(gb);
            float2 gf = *reinterpret_cast<const float2*>(gb + (size_t)HH * BB);
            float2 gg = *reinterpret_cast<const float2*>(gb + (size_t)2 * HH * BB);
            float2 go = *reinterpret_cast<const float2*>(gb + (size_t)3 * HH * BB);

            int sidx = (d2 * HH + h) * BB + b;
            float2 cp = *reinterpret_cast<float2*>(&g_c[sidx]);
            float2 hp = *reinterpret_cast<float2*>(&g_h[sidx]);
            float2 mt = *reinterpret_cast<const float2*>(mask + t2 * BB + b);

            float2 hm, cm;
            {
                float cnew = fsig(gf.x) * cp.x + fsig(gi.x) * ftanh(gg.x);
                float hnew = fsig(go.x) * ftanh(cnew);
                hm.x = hnew * mt.x + hp.x * (1.f - mt.x);
                cm.x = cnew * mt.x + cp.x * (1.f - mt.x);
            }
            {
                float cnew = fsig(gf.y) * cp.y + fsig(gi.y) * ftanh(gg.y);
                float hnew = fsig(go.y) * ftanh(cnew);
                hm.y = hnew * mt.y + hp.y * (1.f - mt.y);
                cm.y = cnew * mt.y + cp.y * (1.f - mt.y);
            }

            *reinterpret_cast<float2*>(&g_h[sidx]) = hm;
            *reinterpret_cast<float2*>(&g_c[sidx]) = cm;

            // A = h * noise for next step's GEMM (coalesced, noise pre-transposed)
            #pragma unroll
            for (int g = 0; g < 4; g++) {
                int ai = (((d2 * 4 + g) * HH) + h) * BB + b;
                float2 nz = *reinterpret_cast<const float2*>(&g_noiseT[ai]);
                *reinterpret_cast<float2*>(&g_A[ai]) = make_float2(hm.x * nz.x, hm.y * nz.y);
            }

            size_t ob = (size_t)t2 * BB * 2 * HH + (size_t)b * 2 * HH + d2 * HH + h;
            op[ob] = hm.x;
            op[ob + 2 * HH] = hm.y;

            if (step == TT - 1) {
                size_t oi = ((size_t)(layer * 2 + d2) * BB + b) * HH + h;
                hn[oi] = hm.x; hn[oi + HH] = hm.y;
                cn[oi] = cm.x; cn[oi + HH] = cm.y;
            }
        }

        grid_barrier();
    }
}

// -------------------- launch --------------------
extern "C" void kernel_launch(void* const* d_in, const int* in_sizes, int n_in,
                              void* d_out, int out_size)
{
    const float* x      = (const float*)d_in[0];
    const float* mask   = (const float*)d_in[1];
    const float* w_ih0  = (const float*)d_in[2];
    const float* w_hh0  = (const float*)d_in[3];
    const float* b_ih0  = (const float*)d_in[4];
    const float* b_hh0  = (const float*)d_in[5];
    const float* n_in0  = (const float*)d_in[6];
    const float* n_hid0 = (const float*)d_in[7];
    const float* w_ih1  = (const float*)d_in[8];
    const float* w_hh1  = (const float*)d_in[9];
    const float* b_ih1  = (const float*)d_in[10];
    const float* b_hh1  = (const float*)d_in[11];
    const float* n_in1  = (const float*)d_in[12];
    const float* n_hid1 = (const float*)d_in[13];

    float* out  = (float*)d_out;
    float* hn   = out + (size_t)TT * BB * 2 * HH;
    float* cn   = hn + (size_t)4 * BB * HH;

    static bool attr_set = false;
    if (!attr_set) {
        cudaFuncSetAttribute(recur_kernel,
                             cudaFuncAttributeMaxDynamicSharedMemorySize, 131072);
        attr_set = true;
    }

    dim3 gxgrid(HH / 64, TT, 8);
    dim3 ntgrid(16, 2, 8);
    dim3 ntblk(32, 8);

    // layer 0
    noiseT_kernel<<<ntgrid, ntblk>>>(n_hid0);
    gx_gemm_kernel<512><<<gxgrid, 128>>>(x, n_in0, w_ih0, b_ih0, b_hh0);
    recur_kernel<<<RC_CTAS, 256, 131072>>>(w_hh0, mask, out, 0, hn, cn);

    // layer 1
    noiseT_kernel<<<ntgrid, ntblk>>>(n_hid1);
    gx_gemm_kernel<1024><<<gxgrid, 128>>>(nullptr, n_in1, w_ih1, b_ih1, b_hh1);
    recur_kernel<<<RC_CTAS, 256, 131072>>>(w_hh1, mask, out, 1, hn, cn);
}